// round 15
// baseline (speedup 1.0000x reference)
#include <cuda_runtime.h>
#include <cuda_fp16.h>

#define INV_SQRT2 0.70710678118654752440f

// Inter-level lowpass scratch (fp16), PLANAR layout [tree][b][c][H][W]
__device__ __half g_lo1[4 * 8 * 3 * 256 * 256];
__device__ __half g_lo2[4 * 8 * 3 * 128 * 128];

// ---- Filter taps as compile-time constants (Farras + Kingsbury Q-shift) ----
#define C_F ((float)0.08838834764832)
#define C_G ((float)0.01122679215254)
#define C_H ((float)0.69587998903400)
#define C_A ((float)0.03516384)
#define C_B ((float)0.08832942)
#define C_C ((float)0.23389032)
#define C_D ((float)0.76027237)
#define C_E ((float)0.58751830)
#define C_K ((float)0.11430184)

__device__ __forceinline__ constexpr float FTAP(int m, int lh, int u) {
    constexpr float T[2][2][10] = {
        {{0.f, -C_F, C_F, C_H, C_H, C_F, -C_F, C_G, C_G, 0.f},
         {0.f, -C_G, C_G, C_F, C_F, -C_H, C_H, -C_F, -C_F, 0.f}},
        {{C_G, C_G, -C_F, C_F, C_H, C_H, C_F, -C_F, 0.f, 0.f},
         {0.f, 0.f, -C_F, -C_F, C_H, -C_H, C_F, C_F, C_G, -C_G}}};
    return T[m][lh][u];
}
__device__ __forceinline__ constexpr float DTAP(int m, int lh, int u) {
    constexpr float T[2][2][10] = {
        {{C_A, 0.f, -C_B, C_C, C_D, C_E, 0.f, -C_K, 0.f, 0.f},
         {0.f, 0.f, -C_K, 0.f, C_E, -C_D, C_C, C_B, 0.f, -C_A}},
        {{0.f, 0.f, -C_K, 0.f, C_E, C_D, C_C, -C_B, 0.f, C_A},
         {-C_A, 0.f, C_B, C_C, -C_D, C_E, 0.f, -C_K, 0.f, 0.f}}};
    return T[m][lh][u];
}
__device__ __forceinline__ constexpr float TAP(int bank, int m, int lh, int u) {
    return bank ? DTAP(m, lh, u) : FTAP(m, lh, u);
}

__device__ __forceinline__ void fma4(float4& a, float C, float4 x) {
    a.x += C * x.x; a.y += C * x.y; a.z += C * x.z; a.w += C * x.w;
}

// Column conv with compile-time tap scaling: SL/SH: 0 = 1.0, 1 = 1/sqrt2.
template <int BANK, int N, int SL, int SH>
__device__ __forceinline__ void colconv(const float r[12], float lo[2], float hi[2]) {
    lo[0] = lo[1] = hi[0] = hi[1] = 0.f;
#pragma unroll
    for (int u = 0; u < 10; u++) {
        const float L = TAP(BANK, N, 0, 9 - u) * (SL ? INV_SQRT2 : 1.0f);
        const float H = TAP(BANK, N, 1, 9 - u) * (SH ? INV_SQRT2 : 1.0f);
#pragma unroll
        for (int p = 0; p < 2; p++) {
            float xv = r[2 * p + u];
            if (L != 0.f) lo[p] += L * xv;
            if (H != 0.f) hi[p] += H * xv;
        }
    }
}

// Load a 12-half window (3x LDS.64) from an fp16 plane, expand to fp32.
template <int PC, int SRS_H>
__device__ __forceinline__ void load12h(const __half* s_row, int plane, int i, int jp, float* r) {
    const __half* p = s_row + plane * SRS_H + i * PC + 4 * jp;   // 8B aligned
    const uint2* p2 = (const uint2*)p;
#pragma unroll
    for (int q = 0; q < 3; q++) {
        uint2 v = p2[q];
        float2 f0 = __half22float2(*(__half2*)&v.x);
        float2 f1 = __half22float2(*(__half2*)&v.y);
        r[4 * q] = f0.x; r[4 * q + 1] = f0.y; r[4 * q + 2] = f1.x; r[4 * q + 3] = f1.y;
    }
}

// Load 4 halves (one LDS.64) -> float4.
__device__ __forceinline__ float4 ld4h(const __half* p) {
    uint2 v = *(const uint2*)p;
    float2 f0 = __half22float2(*(__half2*)&v.x);
    float2 f1 = __half22float2(*(__half2*)&v.y);
    return make_float4(f0.x, f0.y, f1.x, f1.y);
}

// Store 4 floats as 4 halves (one 8B STS).
__device__ __forceinline__ void st4h(__half* p, float4 v) {
    __half2 a = __floats2half2_rn(v.x, v.y);
    __half2 b = __floats2half2_rn(v.z, v.w);
    uint2 u;
    u.x = *(unsigned*)&a; u.y = *(unsigned*)&b;
    *(uint2*)p = u;
}

// Store 2 floats as one 4B __half2.
__device__ __forceinline__ void st2h(__half* p, float a, float b) {
    __half2 h = __floats2half2_rn(a, b);
    *(__half2*)p = h;
}

// =============================== Level 1 ===================================
template <int TI, int TJ>
__global__ __launch_bounds__(256, 5) void afb_l1(
    const float* __restrict__ x, __half* __restrict__ lo1, float* __restrict__ out)
{
    constexpr int PR = 2 * TI + 8, PC = 2 * TJ + 8, JP = TJ / 2;
    constexpr int CS_H = PR * PC + 8;    // halves, mult of 4
    constexpr int SRS_H = TI * PC + 8;   // halves
    constexpr int PCQ = PC / 4;          // 18
    extern __shared__ __align__(16) char smb[];
    __half* s_in = (__half*)smb;                 // [c][PR][PC] fp16
    __half* s_row = s_in + 3 * CS_H;             // [(m*2+lh)*3+c][TI][PC] fp16

    const int tid = threadIdx.x, b = blockIdx.y;
    constexpr int TW = 256 / TJ;
    const int i0 = (blockIdx.x / TW) * TI, j0 = (blockIdx.x % TW) * TJ;
    const int g0r = 2 * i0 - 4, g0c = 2 * j0 - 4;
    const float* xb = x + b * (512 * 512 * 3);

    // ---- Load: vectorized LDG.128 over 4-float column groups ----
    // Linear columns L = pc*3+c (216 floats/row = 54 uint4 groups),
    // 4 row segments of 6 rows. Fast path requires column-interior tile.
    const bool colFast = (g0c >= 0) && (g0c + PC <= 512);
    if (colFast) {
        constexpr int NG = (PC * 3) / 4;     // 54
        constexpr int NSEG = 4, RSEG = PR / NSEG;  // 6
        for (int s = tid; s < NG * NSEG; s += 256) {
            int g = s % NG, seg = s / NG;
            int L = 4 * g;
            int pcs[4], ccs[4];
#pragma unroll
            for (int e = 0; e < 4; e++) { pcs[e] = (L + e) / 3; ccs[e] = (L + e) - 3 * pcs[e]; }
            const float* gbase = xb + g0c * 3 + 4 * g;
            const int pr0 = seg * RSEG;
#pragma unroll
            for (int k = 0; k < RSEG; k++) {
                int pr = pr0 + k;
                int h = g0r + pr; if (h < 0) h += 512; if (h >= 512) h -= 512;
                float4 v = *(const float4*)(gbase + h * 1536);
                s_in[ccs[0] * CS_H + pr * PC + pcs[0]] = __float2half_rn(v.x);
                s_in[ccs[1] * CS_H + pr * PC + pcs[1]] = __float2half_rn(v.y);
                s_in[ccs[2] * CS_H + pr * PC + pcs[2]] = __float2half_rn(v.z);
                s_in[ccs[3] * CS_H + pr * PC + pcs[3]] = __float2half_rn(v.w);
            }
        }
    } else if (tid < PC * 3) {
        int pc = tid / 3, c = tid - 3 * pc;
        int wv = g0c + pc; if (wv < 0) wv += 512; if (wv >= 512) wv -= 512;
        const float* gp = xb + wv * 3 + c;
        __half* sp = s_in + c * CS_H + pc;
#pragma unroll
        for (int pr = 0; pr < PR; pr++) {
            int h = g0r + pr; if (h < 0) h += 512; if (h >= 512) h -= 512;
            sp[pr * PC] = __float2half_rn(gp[h * 1536]);
        }
    }
    __syncthreads();

    // ---- Fused row pass: both m trees from one sweep; taps scaled by 0.5 ----
    if (tid < (TI / 2) * 3 * PCQ) {
        int q = tid % PCQ;
        int t = tid / PCQ;
        int c = t % 3, i2 = t / 3;
        const __half* pin = s_in + c * CS_H + (4 * i2) * PC + 4 * q;
        float4 acc[8];  // [m][lh][row]
#pragma unroll
        for (int k = 0; k < 8; k++) acc[k] = make_float4(0.f, 0.f, 0.f, 0.f);
#pragma unroll
        for (int u = 0; u < 12; u++) {
            float4 xv = ld4h(pin + u * PC);
#pragma unroll
            for (int m = 0; m < 2; m++)
#pragma unroll
                for (int lh = 0; lh < 2; lh++) {
                    const float C0 = ((u < 10) ? FTAP(m, lh, 9 - u) : 0.f) * 0.5f;
                    const float C1 = ((u >= 2) ? FTAP(m, lh, 11 - u) : 0.f) * 0.5f;
                    if (C0 != 0.f) fma4(acc[m * 4 + lh * 2 + 0], C0, xv);
                    if (C1 != 0.f) fma4(acc[m * 4 + lh * 2 + 1], C1, xv);
                }
        }
#pragma unroll
        for (int m = 0; m < 2; m++)
#pragma unroll
            for (int lh = 0; lh < 2; lh++) {
                __half* po = s_row + ((m * 2 + lh) * 3 + c) * SRS_H + (2 * i2) * PC + 4 * q;
                st4h(po, acc[m * 4 + lh * 2 + 0]);
                st4h(po + PC, acc[m * 4 + lh * 2 + 1]);
            }
    }
    __syncthreads();

    // ---- Col pass: tasks (set, i, jp, c) ----
    float* ob = out + b * (1024 * 1024 * 3);
    constexpr int NT = 2 * TI * JP * 3;    // 768
    for (int idx = tid; idx < NT; idx += 256) {
        int c = idx % 3;
        int t = idx / 3;
        int jp = t & (JP - 1); t >>= 4;
        int i = t & (TI - 1);
        int set = t >> 3;
        const int oi = i0 + i, oj = j0 + 2 * jp;

        float W0[12], W1[12];
        load12h<PC, SRS_H>(s_row, (0 + set) * 3 + c, i, jp, W0);  // m=0, lh=set
        load12h<PC, SRS_H>(s_row, (2 + set) * 3 + c, i, jp, W1);  // m=1, lh=set

        if (set == 0) {
            float a_lo[2], a_hi[2], b_lo[2], b_hi[2];
            float c_lo[2], c_hi[2], d_lo[2], d_hi[2];
            colconv<0, 0, 0, 1>(W0, a_lo, a_hi);   // lo unscaled (lo1), hi pre-scaled
            colconv<0, 1, 0, 1>(W0, b_lo, b_hi);
            colconv<0, 0, 0, 1>(W1, c_lo, c_hi);
            colconv<0, 1, 0, 1>(W1, d_lo, d_hi);
            // lowpass -> lo1 PLANAR [tree][b][c][256][256], half2 stores
            {
                __half* pl = lo1 + ((b * 3 + c) * 65536 + oi * 256 + oj);
                constexpr int TS = 8 * 3 * 65536;
                st2h(pl,          a_lo[0], a_lo[1]);
                st2h(pl + TS,     b_lo[0], b_lo[1]);
                st2h(pl + 2 * TS, c_lo[0], c_lo[1]);
                st2h(pl + 3 * TS, d_lo[0], d_lo[1]);
            }
            // LH subband @ (0, 256): taps pre-scaled, pure add/sub
#pragma unroll
            for (int p = 0; p < 2; p++) {
                int r = oi, cc = 256 + oj + p;
                ob[(r * 1024 + cc) * 3 + c]               = a_hi[p] + d_hi[p];
                ob[(r * 1024 + 512 + cc) * 3 + c]         = b_hi[p] + c_hi[p];
                ob[((512 + r) * 1024 + cc) * 3 + c]       = b_hi[p] - c_hi[p];
                ob[((512 + r) * 1024 + 512 + cc) * 3 + c] = a_hi[p] - d_hi[p];
            }
        } else {
            float a_lo[2], a_hi[2], b_lo[2], b_hi[2];
            float c_lo[2], c_hi[2], d_lo[2], d_hi[2];
            colconv<0, 0, 1, 1>(W0, a_lo, a_hi);   // both pre-scaled
            colconv<0, 1, 1, 1>(W0, b_lo, b_hi);
            colconv<0, 0, 1, 1>(W1, c_lo, c_hi);
            colconv<0, 1, 1, 1>(W1, d_lo, d_hi);
            // HL @ (256,0) from lo accs; HH @ (256,256) from hi accs
#pragma unroll
            for (int s = 0; s < 2; s++) {
#pragma unroll
                for (int p = 0; p < 2; p++) {
                    float a0 = s == 0 ? a_lo[p] : a_hi[p];
                    float a1 = s == 0 ? b_lo[p] : b_hi[p];
                    float a2 = s == 0 ? c_lo[p] : c_hi[p];
                    float a3 = s == 0 ? d_lo[p] : d_hi[p];
                    int r = 256 + oi, cc = (s == 0 ? 0 : 256) + oj + p;
                    ob[(r * 1024 + cc) * 3 + c]               = a0 + a3;
                    ob[(r * 1024 + 512 + cc) * 3 + c]         = a1 + a2;
                    ob[((512 + r) * 1024 + cc) * 3 + c]       = a1 - a2;
                    ob[((512 + r) * 1024 + 512 + cc) * 3 + c] = a0 - a3;
                }
            }
        }
    }
}

// ============================ Levels 2 and 3 ===============================
// Pair P: slot0 = tree P (row m=0, col n=P), slot1 = tree 3-P (m=1, n=1-P).
// lo_in/lo_out PLANAR [tree][b][c][H][W].
template <int P, int TI, int TJ, int Hin, int SBS, bool FINAL>
__device__ __forceinline__ void l23_body(
    const __half* __restrict__ lo_in, __half* __restrict__ lo_out,
    float* __restrict__ out, int b, __half* smh)
{
    constexpr int PR = 2 * TI + 8, PC = 2 * TJ + 8, JP = TJ / 2;
    constexpr int CS_H = PR * PC + 8;
    constexpr int SRS_H = TI * PC + 8;
    constexpr int PCQ = PC / 4;
    constexpr int Hout = Hin / 2;
    __half* s_in = smh;                       // [slot*3+c][PR][PC] fp16
    __half* s_row = smh + 6 * CS_H;           // [(slot*2+lh)*3+c][TI][PC] fp16

    const int tid = threadIdx.x;
    constexpr int TW = Hout / TJ;
    const int i0 = (blockIdx.x / TW) * TI, j0 = (blockIdx.x % TW) * TJ;
    const int g0r = 2 * i0 - 4, g0c = 2 * j0 - 4;

    // ---- Load both slots: planar, 4-wide pc groups, uint2 fast path ----
    {
        constexpr int NSEG = 4;
        constexpr int RSEG = PR / NSEG;              // PR mult of 4
        constexpr int NLT = 2 * 3 * PCQ * NSEG;
        const bool colFast = (g0c >= 0) && (g0c + PC <= Hin);
        for (int s = tid; s < NLT; s += 256) {
            int q = s % PCQ;
            int t = s / PCQ;
            int seg = t % NSEG; t /= NSEG;
            int c = t % 3, slot = t / 3;
            const int tr = slot ? (3 - P) : P;
            const __half* plane = lo_in + ((tr * 8 + b) * 3 + c) * (Hin * Hin);
            __half* sp = s_in + (slot * 3 + c) * CS_H + q * 4;
            const int pr0 = seg * RSEG;
            if (colFast) {
                const __half* gq = plane + (g0c + 4 * q);
#pragma unroll
                for (int k = 0; k < RSEG; k++) {
                    int pr = pr0 + k;
                    int h = g0r + pr; if (h < 0) h += Hin; if (h >= Hin) h -= Hin;
                    *(uint2*)(sp + pr * PC) = *(const uint2*)(gq + h * Hin);
                }
            } else {
#pragma unroll
                for (int k = 0; k < RSEG; k++) {
                    int pr = pr0 + k;
                    int h = g0r + pr; if (h < 0) h += Hin; if (h >= Hin) h -= Hin;
                    const __half* gr = plane + h * Hin;
#pragma unroll
                    for (int e = 0; e < 4; e++) {
                        int w = g0c + 4 * q + e; if (w < 0) w += Hin; if (w >= Hin) w -= Hin;
                        sp[pr * PC + e] = gr[w];
                    }
                }
            }
        }
    }
    __syncthreads();

    // ---- Row pass: both slots; m = slot ----
    constexpr int HALF = (TI / 2) * 3 * PCQ;
    for (int s = tid; s < 2 * HALF; s += 256) {
        int slot = s >= HALF;
        int rem = s - slot * HALF;
        int q = rem % PCQ;
        int t = rem / PCQ;
        int c = t % 3, i2 = t / 3;
        const __half* pin = s_in + (slot * 3 + c) * CS_H + (4 * i2) * PC + 4 * q;
        float4 acc[4];  // [lh][row]
#pragma unroll
        for (int k = 0; k < 4; k++) acc[k] = make_float4(0.f, 0.f, 0.f, 0.f);
        if (slot == 0) {
#pragma unroll
            for (int u = 0; u < 12; u++) {
                float4 xv = ld4h(pin + u * PC);
#pragma unroll
                for (int lh = 0; lh < 2; lh++) {
                    const float C0 = (u < 10) ? DTAP(0, lh, 9 - u) : 0.f;
                    const float C1 = (u >= 2) ? DTAP(0, lh, 11 - u) : 0.f;
                    if (C0 != 0.f) fma4(acc[lh * 2 + 0], C0, xv);
                    if (C1 != 0.f) fma4(acc[lh * 2 + 1], C1, xv);
                }
            }
        } else {
#pragma unroll
            for (int u = 0; u < 12; u++) {
                float4 xv = ld4h(pin + u * PC);
#pragma unroll
                for (int lh = 0; lh < 2; lh++) {
                    const float C0 = (u < 10) ? DTAP(1, lh, 9 - u) : 0.f;
                    const float C1 = (u >= 2) ? DTAP(1, lh, 11 - u) : 0.f;
                    if (C0 != 0.f) fma4(acc[lh * 2 + 0], C0, xv);
                    if (C1 != 0.f) fma4(acc[lh * 2 + 1], C1, xv);
                }
            }
        }
#pragma unroll
        for (int lh = 0; lh < 2; lh++) {
            __half* po = s_row + ((slot * 2 + lh) * 3 + c) * SRS_H + (2 * i2) * PC + 4 * q;
            st4h(po, acc[lh * 2 + 0]);
            st4h(po + PC, acc[lh * 2 + 1]);
        }
    }
    __syncthreads();

    // ---- Col pass ----
    constexpr int N0 = P, N1 = 1 - P;
    float* ob = out + b * (1024 * 1024 * 3);
    constexpr int NT = 2 * TI * JP * 3;
    for (int idx = tid; idx < NT; idx += 256) {
        const int jp = idx % JP;
        int t = idx / JP;
        const int i = t % TI; t /= TI;
        const int set = t % 2;
        const int c = t / 2;
        const int oi = i0 + i, oj = j0 + 2 * jp;

        float W0[12], W1[12];
        load12h<PC, SRS_H>(s_row, (0 + set) * 3 + c, i, jp, W0);  // slot0, lh=set
        load12h<PC, SRS_H>(s_row, (2 + set) * 3 + c, i, jp, W1);  // slot1, lh=set

        if (set == 0) {
            float A_lo[2], A_hi[2], B_lo[2], B_hi[2];
            colconv<1, N0, 0, 1>(W0, A_lo, A_hi);
            colconv<1, N1, 0, 1>(W1, B_lo, B_hi);
            if (FINAL) {
#pragma unroll
                for (int p = 0; p < 2; p++) {
                    ob[(oi * 1024 + P * 512 + oj + p) * 3 + c] = A_lo[p];
                    ob[((512 + oi) * 1024 + (1 - P) * 512 + oj + p) * 3 + c] = B_lo[p];
                }
            } else {
                __half* plA = lo_out + ((P * 8 + b) * 3 + c) * (Hout * Hout) + oi * Hout + oj;
                st2h(plA, A_lo[0], A_lo[1]);
                __half* plB = lo_out + (((3 - P) * 8 + b) * 3 + c) * (Hout * Hout) + oi * Hout + oj;
                st2h(plB, B_lo[0], B_lo[1]);
            }
            // LH @ (0, SBS), pre-scaled
#pragma unroll
            for (int p = 0; p < 2; p++) {
                int r = oi, cc = SBS + oj + p;
                ob[(r * 1024 + P * 512 + cc) * 3 + c] = A_hi[p] + B_hi[p];
                ob[((512 + r) * 1024 + (1 - P) * 512 + cc) * 3 + c] = A_hi[p] - B_hi[p];
            }
        } else {
            float A_lo[2], A_hi[2], B_lo[2], B_hi[2];
            colconv<1, N0, 1, 1>(W0, A_lo, A_hi);
            colconv<1, N1, 1, 1>(W1, B_lo, B_hi);
            // HL @ (SBS,0), HH @ (SBS,SBS), pre-scaled
#pragma unroll
            for (int p = 0; p < 2; p++) {
                int r = SBS + oi;
                ob[(r * 1024 + P * 512 + oj + p) * 3 + c] = A_lo[p] + B_lo[p];
                ob[((512 + r) * 1024 + (1 - P) * 512 + oj + p) * 3 + c] = A_lo[p] - B_lo[p];
                int cc = SBS + oj + p;
                ob[(r * 1024 + P * 512 + cc) * 3 + c] = A_hi[p] + B_hi[p];
                ob[((512 + r) * 1024 + (1 - P) * 512 + cc) * 3 + c] = A_hi[p] - B_hi[p];
            }
        }
    }
}

template <int TI, int TJ, int Hin, int SBS, bool FINAL>
__global__ __launch_bounds__(256, 5) void afb_l23(
    const __half* __restrict__ lo_in, __half* __restrict__ lo_out,
    float* __restrict__ out)
{
    extern __shared__ __align__(16) char smb[];
    const int p = blockIdx.y >> 3, b = blockIdx.y & 7;
    if (p == 0) l23_body<0, TI, TJ, Hin, SBS, FINAL>(lo_in, lo_out, out, b, (__half*)smb);
    else        l23_body<1, TI, TJ, Hin, SBS, FINAL>(lo_in, lo_out, out, b, (__half*)smb);
}

extern "C" void kernel_launch(void* const* d_in, const int* in_sizes, int n_in,
                              void* d_out, int out_size)
{
    const float* x = (const float*)d_in[0];
    float* out = (float*)d_out;

    __half *lo1, *lo2;
    cudaGetSymbolAddress((void**)&lo1, g_lo1);
    cudaGetSymbolAddress((void**)&lo2, g_lo2);

    // Level 1: x (512) -> subbands(256) + lo1(256)
    {
        constexpr int TI = 8, TJ = 32;
        constexpr int CS_H = (2 * TI + 8) * (2 * TJ + 8) + 8; // 1736 halves
        constexpr int SRS_H = TI * (2 * TJ + 8) + 8;          // 584 halves
        dim3 grid((256 / TI) * (256 / TJ), 8);                // 256 x 8
        size_t smem = 3 * CS_H * 2 + 12 * SRS_H * 2;          // 24432 B
        afb_l1<TI, TJ><<<grid, 256, smem>>>(x, lo1, out);
    }
    // Level 2: lo1 (256) -> subbands(128) + lo2(128), tile 8x16 (2048 CTAs)
    {
        constexpr int TI = 8, TJ = 16, H = 256;
        constexpr int CS_H = (2 * TI + 8) * (2 * TJ + 8) + 8; // 968 halves
        constexpr int SRS_H = TI * (2 * TJ + 8) + 8;          // 328
        dim3 grid((128 / TI) * (128 / TJ), 16);               // 128 x 16
        size_t smem = 6 * CS_H * 2 + 12 * SRS_H * 2;          // 19488 B
        afb_l23<TI, TJ, H, 128, false><<<grid, 256, smem>>>(lo1, lo2, out);
    }
    // Level 3: lo2 (128) -> subbands(64) + raw lowpass, tile 4x8 (2048 CTAs)
    {
        constexpr int TI = 4, TJ = 8, H = 128;
        constexpr int CS_H = (2 * TI + 8) * (2 * TJ + 8) + 8; // 392
        constexpr int SRS_H = TI * (2 * TJ + 8) + 8;          // 104
        dim3 grid((64 / TI) * (64 / TJ), 16);                 // 128 x 16
        size_t smem = 6 * CS_H * 2 + 12 * SRS_H * 2;          // 7200 B
        afb_l23<TI, TJ, H, 64, true><<<grid, 256, smem>>>(lo2, nullptr, out);
    }
}

// round 16
// speedup vs baseline: 1.0631x; 1.0631x over previous
#include <cuda_runtime.h>
#include <cuda_fp16.h>

#define INV_SQRT2 0.70710678118654752440f

// Inter-level lowpass scratch (fp16), PLANAR layout [tree][b][c][H][W]
__device__ __half g_lo1[4 * 8 * 3 * 256 * 256];
__device__ __half g_lo2[4 * 8 * 3 * 128 * 128];

// ---- Filter taps as compile-time constants (Farras + Kingsbury Q-shift) ----
#define C_F ((float)0.08838834764832)
#define C_G ((float)0.01122679215254)
#define C_H ((float)0.69587998903400)
#define C_A ((float)0.03516384)
#define C_B ((float)0.08832942)
#define C_C ((float)0.23389032)
#define C_D ((float)0.76027237)
#define C_E ((float)0.58751830)
#define C_K ((float)0.11430184)

__device__ __forceinline__ constexpr float FTAP(int m, int lh, int u) {
    constexpr float T[2][2][10] = {
        {{0.f, -C_F, C_F, C_H, C_H, C_F, -C_F, C_G, C_G, 0.f},
         {0.f, -C_G, C_G, C_F, C_F, -C_H, C_H, -C_F, -C_F, 0.f}},
        {{C_G, C_G, -C_F, C_F, C_H, C_H, C_F, -C_F, 0.f, 0.f},
         {0.f, 0.f, -C_F, -C_F, C_H, -C_H, C_F, C_F, C_G, -C_G}}};
    return T[m][lh][u];
}
__device__ __forceinline__ constexpr float DTAP(int m, int lh, int u) {
    constexpr float T[2][2][10] = {
        {{C_A, 0.f, -C_B, C_C, C_D, C_E, 0.f, -C_K, 0.f, 0.f},
         {0.f, 0.f, -C_K, 0.f, C_E, -C_D, C_C, C_B, 0.f, -C_A}},
        {{0.f, 0.f, -C_K, 0.f, C_E, C_D, C_C, -C_B, 0.f, C_A},
         {-C_A, 0.f, C_B, C_C, -C_D, C_E, 0.f, -C_K, 0.f, 0.f}}};
    return T[m][lh][u];
}
__device__ __forceinline__ constexpr float TAP(int bank, int m, int lh, int u) {
    return bank ? DTAP(m, lh, u) : FTAP(m, lh, u);
}

__device__ __forceinline__ void fma4(float4& a, float C, float4 x) {
    a.x += C * x.x; a.y += C * x.y; a.z += C * x.z; a.w += C * x.w;
}

// Streaming (evict-first) global store for write-once output.
__device__ __forceinline__ void stcs(float* p, float v) {
    __stcs(p, v);
}

// Column conv with compile-time tap scaling: SL/SH: 0 = 1.0, 1 = 1/sqrt2.
template <int BANK, int N, int SL, int SH>
__device__ __forceinline__ void colconv(const float r[12], float lo[2], float hi[2]) {
    lo[0] = lo[1] = hi[0] = hi[1] = 0.f;
#pragma unroll
    for (int u = 0; u < 10; u++) {
        const float L = TAP(BANK, N, 0, 9 - u) * (SL ? INV_SQRT2 : 1.0f);
        const float H = TAP(BANK, N, 1, 9 - u) * (SH ? INV_SQRT2 : 1.0f);
#pragma unroll
        for (int p = 0; p < 2; p++) {
            float xv = r[2 * p + u];
            if (L != 0.f) lo[p] += L * xv;
            if (H != 0.f) hi[p] += H * xv;
        }
    }
}

// Load a 12-half window (3x LDS.64) from an fp16 plane, expand to fp32.
template <int PC, int SRS_H>
__device__ __forceinline__ void load12h(const __half* s_row, int plane, int i, int jp, float* r) {
    const __half* p = s_row + plane * SRS_H + i * PC + 4 * jp;   // 8B aligned
    const uint2* p2 = (const uint2*)p;
#pragma unroll
    for (int q = 0; q < 3; q++) {
        uint2 v = p2[q];
        float2 f0 = __half22float2(*(__half2*)&v.x);
        float2 f1 = __half22float2(*(__half2*)&v.y);
        r[4 * q] = f0.x; r[4 * q + 1] = f0.y; r[4 * q + 2] = f1.x; r[4 * q + 3] = f1.y;
    }
}

// Load 4 halves (one LDS.64) -> float4.
__device__ __forceinline__ float4 ld4h(const __half* p) {
    uint2 v = *(const uint2*)p;
    float2 f0 = __half22float2(*(__half2*)&v.x);
    float2 f1 = __half22float2(*(__half2*)&v.y);
    return make_float4(f0.x, f0.y, f1.x, f1.y);
}

// Store 4 floats as 4 halves (one 8B STS).
__device__ __forceinline__ void st4h(__half* p, float4 v) {
    __half2 a = __floats2half2_rn(v.x, v.y);
    __half2 b = __floats2half2_rn(v.z, v.w);
    uint2 u;
    u.x = *(unsigned*)&a; u.y = *(unsigned*)&b;
    *(uint2*)p = u;
}

// Store 2 floats as one 4B __half2.
__device__ __forceinline__ void st2h(__half* p, float a, float b) {
    __half2 h = __floats2half2_rn(a, b);
    *(__half2*)p = h;
}

// =============================== Level 1 ===================================
template <int TI, int TJ>
__global__ __launch_bounds__(256, 5) void afb_l1(
    const float* __restrict__ x, __half* __restrict__ lo1, float* __restrict__ out)
{
    constexpr int PR = 2 * TI + 8, PC = 2 * TJ + 8, JP = TJ / 2;
    constexpr int CS_H = PR * PC + 8;    // halves, mult of 4
    constexpr int SRS_H = TI * PC + 8;   // halves
    constexpr int PCQ = PC / 4;          // 18
    extern __shared__ __align__(16) char smb[];
    __half* s_in = (__half*)smb;                 // [c][PR][PC] fp16
    __half* s_row = s_in + 3 * CS_H;             // [(m*2+lh)*3+c][TI][PC] fp16

    const int tid = threadIdx.x, b = blockIdx.y;
    constexpr int TW = 256 / TJ;
    const int i0 = (blockIdx.x / TW) * TI, j0 = (blockIdx.x % TW) * TJ;
    const int g0r = 2 * i0 - 4, g0c = 2 * j0 - 4;
    const float* xb = x + b * (512 * 512 * 3);

    // ---- Load: thread owns (pc,c) column, walks PR rows, fp32->fp16 ----
    if (tid < PC * 3) {
        int pc = tid / 3, c = tid - 3 * pc;
        int wv = g0c + pc; if (wv < 0) wv += 512; if (wv >= 512) wv -= 512;
        const float* gp = xb + wv * 3 + c;
        __half* sp = s_in + c * CS_H + pc;
        if (g0r >= 0 && g0r + PR <= 512) {
            const float* gr = gp + g0r * 1536;
#pragma unroll
            for (int pr = 0; pr < PR; pr++)
                sp[pr * PC] = __float2half_rn(gr[pr * 1536]);
        } else {
#pragma unroll
            for (int pr = 0; pr < PR; pr++) {
                int h = g0r + pr; if (h < 0) h += 512; if (h >= 512) h -= 512;
                sp[pr * PC] = __float2half_rn(gp[h * 1536]);
            }
        }
    }
    __syncthreads();

    // ---- Fused row pass: both m trees from one sweep; taps scaled by 0.5 ----
    if (tid < (TI / 2) * 3 * PCQ) {
        int q = tid % PCQ;
        int t = tid / PCQ;
        int c = t % 3, i2 = t / 3;
        const __half* pin = s_in + c * CS_H + (4 * i2) * PC + 4 * q;
        float4 acc[8];  // [m][lh][row]
#pragma unroll
        for (int k = 0; k < 8; k++) acc[k] = make_float4(0.f, 0.f, 0.f, 0.f);
#pragma unroll
        for (int u = 0; u < 12; u++) {
            float4 xv = ld4h(pin + u * PC);
#pragma unroll
            for (int m = 0; m < 2; m++)
#pragma unroll
                for (int lh = 0; lh < 2; lh++) {
                    const float C0 = ((u < 10) ? FTAP(m, lh, 9 - u) : 0.f) * 0.5f;
                    const float C1 = ((u >= 2) ? FTAP(m, lh, 11 - u) : 0.f) * 0.5f;
                    if (C0 != 0.f) fma4(acc[m * 4 + lh * 2 + 0], C0, xv);
                    if (C1 != 0.f) fma4(acc[m * 4 + lh * 2 + 1], C1, xv);
                }
        }
#pragma unroll
        for (int m = 0; m < 2; m++)
#pragma unroll
            for (int lh = 0; lh < 2; lh++) {
                __half* po = s_row + ((m * 2 + lh) * 3 + c) * SRS_H + (2 * i2) * PC + 4 * q;
                st4h(po, acc[m * 4 + lh * 2 + 0]);
                st4h(po + PC, acc[m * 4 + lh * 2 + 1]);
            }
    }
    __syncthreads();

    // ---- Col pass: tasks (set, i, jp, c) ----
    float* ob = out + b * (1024 * 1024 * 3);
    constexpr int NT = 2 * TI * JP * 3;    // 768
    for (int idx = tid; idx < NT; idx += 256) {
        int c = idx % 3;
        int t = idx / 3;
        int jp = t & (JP - 1); t >>= 4;
        int i = t & (TI - 1);
        int set = t >> 3;
        const int oi = i0 + i, oj = j0 + 2 * jp;

        float W0[12], W1[12];
        load12h<PC, SRS_H>(s_row, (0 + set) * 3 + c, i, jp, W0);  // m=0, lh=set
        load12h<PC, SRS_H>(s_row, (2 + set) * 3 + c, i, jp, W1);  // m=1, lh=set

        if (set == 0) {
            float a_lo[2], a_hi[2], b_lo[2], b_hi[2];
            float c_lo[2], c_hi[2], d_lo[2], d_hi[2];
            colconv<0, 0, 0, 1>(W0, a_lo, a_hi);   // lo unscaled (lo1), hi pre-scaled
            colconv<0, 1, 0, 1>(W0, b_lo, b_hi);
            colconv<0, 0, 0, 1>(W1, c_lo, c_hi);
            colconv<0, 1, 0, 1>(W1, d_lo, d_hi);
            // lowpass -> lo1 PLANAR [tree][b][c][256][256], half2 stores
            {
                __half* pl = lo1 + ((b * 3 + c) * 65536 + oi * 256 + oj);
                constexpr int TS = 8 * 3 * 65536;
                st2h(pl,          a_lo[0], a_lo[1]);
                st2h(pl + TS,     b_lo[0], b_lo[1]);
                st2h(pl + 2 * TS, c_lo[0], c_lo[1]);
                st2h(pl + 3 * TS, d_lo[0], d_lo[1]);
            }
            // LH subband @ (0, 256): taps pre-scaled, pure add/sub
#pragma unroll
            for (int p = 0; p < 2; p++) {
                int r = oi, cc = 256 + oj + p;
                stcs(&ob[(r * 1024 + cc) * 3 + c],               a_hi[p] + d_hi[p]);
                stcs(&ob[(r * 1024 + 512 + cc) * 3 + c],         b_hi[p] + c_hi[p]);
                stcs(&ob[((512 + r) * 1024 + cc) * 3 + c],       b_hi[p] - c_hi[p]);
                stcs(&ob[((512 + r) * 1024 + 512 + cc) * 3 + c], a_hi[p] - d_hi[p]);
            }
        } else {
            float a_lo[2], a_hi[2], b_lo[2], b_hi[2];
            float c_lo[2], c_hi[2], d_lo[2], d_hi[2];
            colconv<0, 0, 1, 1>(W0, a_lo, a_hi);   // both pre-scaled
            colconv<0, 1, 1, 1>(W0, b_lo, b_hi);
            colconv<0, 0, 1, 1>(W1, c_lo, c_hi);
            colconv<0, 1, 1, 1>(W1, d_lo, d_hi);
            // HL @ (256,0) from lo accs; HH @ (256,256) from hi accs
#pragma unroll
            for (int s = 0; s < 2; s++) {
#pragma unroll
                for (int p = 0; p < 2; p++) {
                    float a0 = s == 0 ? a_lo[p] : a_hi[p];
                    float a1 = s == 0 ? b_lo[p] : b_hi[p];
                    float a2 = s == 0 ? c_lo[p] : c_hi[p];
                    float a3 = s == 0 ? d_lo[p] : d_hi[p];
                    int r = 256 + oi, cc = (s == 0 ? 0 : 256) + oj + p;
                    stcs(&ob[(r * 1024 + cc) * 3 + c],               a0 + a3);
                    stcs(&ob[(r * 1024 + 512 + cc) * 3 + c],         a1 + a2);
                    stcs(&ob[((512 + r) * 1024 + cc) * 3 + c],       a1 - a2);
                    stcs(&ob[((512 + r) * 1024 + 512 + cc) * 3 + c], a0 - a3);
                }
            }
        }
    }
}

// ============================ Levels 2 and 3 ===============================
// Pair P: slot0 = tree P (row m=0, col n=P), slot1 = tree 3-P (m=1, n=1-P).
// lo_in/lo_out PLANAR [tree][b][c][H][W].
template <int P, int TI, int TJ, int Hin, int SBS, bool FINAL>
__device__ __forceinline__ void l23_body(
    const __half* __restrict__ lo_in, __half* __restrict__ lo_out,
    float* __restrict__ out, int b, __half* smh)
{
    constexpr int PR = 2 * TI + 8, PC = 2 * TJ + 8, JP = TJ / 2;
    constexpr int CS_H = PR * PC + 8;
    constexpr int SRS_H = TI * PC + 8;
    constexpr int PCQ = PC / 4;
    constexpr int Hout = Hin / 2;
    __half* s_in = smh;                       // [slot*3+c][PR][PC] fp16
    __half* s_row = smh + 6 * CS_H;           // [(slot*2+lh)*3+c][TI][PC] fp16

    const int tid = threadIdx.x;
    constexpr int TW = Hout / TJ;
    const int i0 = (blockIdx.x / TW) * TI, j0 = (blockIdx.x % TW) * TJ;
    const int g0r = 2 * i0 - 4, g0c = 2 * j0 - 4;

    // ---- Load both slots: planar, 4-wide pc groups, uint2 fast path ----
    {
        constexpr int NSEG = 4;
        constexpr int RSEG = PR / NSEG;              // PR mult of 4
        constexpr int NLT = 2 * 3 * PCQ * NSEG;
        const bool colFast = (g0c >= 0) && (g0c + PC <= Hin);
        for (int s = tid; s < NLT; s += 256) {
            int q = s % PCQ;
            int t = s / PCQ;
            int seg = t % NSEG; t /= NSEG;
            int c = t % 3, slot = t / 3;
            const int tr = slot ? (3 - P) : P;
            const __half* plane = lo_in + ((tr * 8 + b) * 3 + c) * (Hin * Hin);
            __half* sp = s_in + (slot * 3 + c) * CS_H + q * 4;
            const int pr0 = seg * RSEG;
            if (colFast) {
                const __half* gq = plane + (g0c + 4 * q);
#pragma unroll
                for (int k = 0; k < RSEG; k++) {
                    int pr = pr0 + k;
                    int h = g0r + pr; if (h < 0) h += Hin; if (h >= Hin) h -= Hin;
                    *(uint2*)(sp + pr * PC) = *(const uint2*)(gq + h * Hin);
                }
            } else {
#pragma unroll
                for (int k = 0; k < RSEG; k++) {
                    int pr = pr0 + k;
                    int h = g0r + pr; if (h < 0) h += Hin; if (h >= Hin) h -= Hin;
                    const __half* gr = plane + h * Hin;
#pragma unroll
                    for (int e = 0; e < 4; e++) {
                        int w = g0c + 4 * q + e; if (w < 0) w += Hin; if (w >= Hin) w -= Hin;
                        sp[pr * PC + e] = gr[w];
                    }
                }
            }
        }
    }
    __syncthreads();

    // ---- Row pass: both slots; m = slot ----
    constexpr int HALF = (TI / 2) * 3 * PCQ;
    for (int s = tid; s < 2 * HALF; s += 256) {
        int slot = s >= HALF;
        int rem = s - slot * HALF;
        int q = rem % PCQ;
        int t = rem / PCQ;
        int c = t % 3, i2 = t / 3;
        const __half* pin = s_in + (slot * 3 + c) * CS_H + (4 * i2) * PC + 4 * q;
        float4 acc[4];  // [lh][row]
#pragma unroll
        for (int k = 0; k < 4; k++) acc[k] = make_float4(0.f, 0.f, 0.f, 0.f);
        if (slot == 0) {
#pragma unroll
            for (int u = 0; u < 12; u++) {
                float4 xv = ld4h(pin + u * PC);
#pragma unroll
                for (int lh = 0; lh < 2; lh++) {
                    const float C0 = (u < 10) ? DTAP(0, lh, 9 - u) : 0.f;
                    const float C1 = (u >= 2) ? DTAP(0, lh, 11 - u) : 0.f;
                    if (C0 != 0.f) fma4(acc[lh * 2 + 0], C0, xv);
                    if (C1 != 0.f) fma4(acc[lh * 2 + 1], C1, xv);
                }
            }
        } else {
#pragma unroll
            for (int u = 0; u < 12; u++) {
                float4 xv = ld4h(pin + u * PC);
#pragma unroll
                for (int lh = 0; lh < 2; lh++) {
                    const float C0 = (u < 10) ? DTAP(1, lh, 9 - u) : 0.f;
                    const float C1 = (u >= 2) ? DTAP(1, lh, 11 - u) : 0.f;
                    if (C0 != 0.f) fma4(acc[lh * 2 + 0], C0, xv);
                    if (C1 != 0.f) fma4(acc[lh * 2 + 1], C1, xv);
                }
            }
        }
#pragma unroll
        for (int lh = 0; lh < 2; lh++) {
            __half* po = s_row + ((slot * 2 + lh) * 3 + c) * SRS_H + (2 * i2) * PC + 4 * q;
            st4h(po, acc[lh * 2 + 0]);
            st4h(po + PC, acc[lh * 2 + 1]);
        }
    }
    __syncthreads();

    // ---- Col pass ----
    constexpr int N0 = P, N1 = 1 - P;
    float* ob = out + b * (1024 * 1024 * 3);
    constexpr int NT = 2 * TI * JP * 3;
    for (int idx = tid; idx < NT; idx += 256) {
        const int jp = idx % JP;
        int t = idx / JP;
        const int i = t % TI; t /= TI;
        const int set = t % 2;
        const int c = t / 2;
        const int oi = i0 + i, oj = j0 + 2 * jp;

        float W0[12], W1[12];
        load12h<PC, SRS_H>(s_row, (0 + set) * 3 + c, i, jp, W0);  // slot0, lh=set
        load12h<PC, SRS_H>(s_row, (2 + set) * 3 + c, i, jp, W1);  // slot1, lh=set

        if (set == 0) {
            float A_lo[2], A_hi[2], B_lo[2], B_hi[2];
            colconv<1, N0, 0, 1>(W0, A_lo, A_hi);
            colconv<1, N1, 0, 1>(W1, B_lo, B_hi);
            if (FINAL) {
#pragma unroll
                for (int p = 0; p < 2; p++) {
                    stcs(&ob[(oi * 1024 + P * 512 + oj + p) * 3 + c], A_lo[p]);
                    stcs(&ob[((512 + oi) * 1024 + (1 - P) * 512 + oj + p) * 3 + c], B_lo[p]);
                }
            } else {
                __half* plA = lo_out + ((P * 8 + b) * 3 + c) * (Hout * Hout) + oi * Hout + oj;
                st2h(plA, A_lo[0], A_lo[1]);
                __half* plB = lo_out + (((3 - P) * 8 + b) * 3 + c) * (Hout * Hout) + oi * Hout + oj;
                st2h(plB, B_lo[0], B_lo[1]);
            }
            // LH @ (0, SBS), pre-scaled
#pragma unroll
            for (int p = 0; p < 2; p++) {
                int r = oi, cc = SBS + oj + p;
                stcs(&ob[(r * 1024 + P * 512 + cc) * 3 + c], A_hi[p] + B_hi[p]);
                stcs(&ob[((512 + r) * 1024 + (1 - P) * 512 + cc) * 3 + c], A_hi[p] - B_hi[p]);
            }
        } else {
            float A_lo[2], A_hi[2], B_lo[2], B_hi[2];
            colconv<1, N0, 1, 1>(W0, A_lo, A_hi);
            colconv<1, N1, 1, 1>(W1, B_lo, B_hi);
            // HL @ (SBS,0), HH @ (SBS,SBS), pre-scaled
#pragma unroll
            for (int p = 0; p < 2; p++) {
                int r = SBS + oi;
                stcs(&ob[(r * 1024 + P * 512 + oj + p) * 3 + c], A_lo[p] + B_lo[p]);
                stcs(&ob[((512 + r) * 1024 + (1 - P) * 512 + oj + p) * 3 + c], A_lo[p] - B_lo[p]);
                int cc = SBS + oj + p;
                stcs(&ob[(r * 1024 + P * 512 + cc) * 3 + c], A_hi[p] + B_hi[p]);
                stcs(&ob[((512 + r) * 1024 + (1 - P) * 512 + cc) * 3 + c], A_hi[p] - B_hi[p]);
            }
        }
    }
}

template <int TI, int TJ, int Hin, int SBS, bool FINAL>
__global__ __launch_bounds__(256, 5) void afb_l23(
    const __half* __restrict__ lo_in, __half* __restrict__ lo_out,
    float* __restrict__ out)
{
    extern __shared__ __align__(16) char smb[];
    const int p = blockIdx.y >> 3, b = blockIdx.y & 7;
    if (p == 0) l23_body<0, TI, TJ, Hin, SBS, FINAL>(lo_in, lo_out, out, b, (__half*)smb);
    else        l23_body<1, TI, TJ, Hin, SBS, FINAL>(lo_in, lo_out, out, b, (__half*)smb);
}

extern "C" void kernel_launch(void* const* d_in, const int* in_sizes, int n_in,
                              void* d_out, int out_size)
{
    const float* x = (const float*)d_in[0];
    float* out = (float*)d_out;

    __half *lo1, *lo2;
    cudaGetSymbolAddress((void**)&lo1, g_lo1);
    cudaGetSymbolAddress((void**)&lo2, g_lo2);

    // Level 1: x (512) -> subbands(256) + lo1(256)
    {
        constexpr int TI = 8, TJ = 32;
        constexpr int CS_H = (2 * TI + 8) * (2 * TJ + 8) + 8; // 1736 halves
        constexpr int SRS_H = TI * (2 * TJ + 8) + 8;          // 584 halves
        dim3 grid((256 / TI) * (256 / TJ), 8);                // 256 x 8
        size_t smem = 3 * CS_H * 2 + 12 * SRS_H * 2;          // 24432 B
        afb_l1<TI, TJ><<<grid, 256, smem>>>(x, lo1, out);
    }
    // Level 2: lo1 (256) -> subbands(128) + lo2(128), tile 8x16 (2048 CTAs)
    {
        constexpr int TI = 8, TJ = 16, H = 256;
        constexpr int CS_H = (2 * TI + 8) * (2 * TJ + 8) + 8; // 968 halves
        constexpr int SRS_H = TI * (2 * TJ + 8) + 8;          // 328
        dim3 grid((128 / TI) * (128 / TJ), 16);               // 128 x 16
        size_t smem = 6 * CS_H * 2 + 12 * SRS_H * 2;          // 19488 B
        afb_l23<TI, TJ, H, 128, false><<<grid, 256, smem>>>(lo1, lo2, out);
    }
    // Level 3: lo2 (128) -> subbands(64) + raw lowpass, tile 4x8 (2048 CTAs)
    {
        constexpr int TI = 4, TJ = 8, H = 128;
        constexpr int CS_H = (2 * TI + 8) * (2 * TJ + 8) + 8; // 392
        constexpr int SRS_H = TI * (2 * TJ + 8) + 8;          // 104
        dim3 grid((64 / TI) * (64 / TJ), 16);                 // 128 x 16
        size_t smem = 6 * CS_H * 2 + 12 * SRS_H * 2;          // 7200 B
        afb_l23<TI, TJ, H, 64, true><<<grid, 256, smem>>>(lo2, nullptr, out);
    }
}